// round 2
// baseline (speedup 1.0000x reference)
#include <cuda_runtime.h>

#define TT 128
#define BB 512
#define QQ 50
#define BQ (BB * QQ)
#define NUNITS ((TT - 1) * BB)     // 65024 (t,b) units with a loss row
#define GAMMA_F 0.99f
#define RST 52                      // padded smem row stride (floats), 16B-aligned
#define UNITS 5                     // (t,b) units per block in pair kernel

// Scratch for discounted returns: [127][B*Q], same layout as inputs. ~13 MB.
__device__ float g_ret[(TT - 1) * BQ];

// ---------------------------------------------------------------------------
// Kernel 1: backward-in-time recurrence. One thread per (b,q) chain.
// Also zeroes the last output row (out buffer is poisoned).
// ---------------------------------------------------------------------------
__global__ __launch_bounds__(512)
void k_returns(const float* __restrict__ reward,
               const int*   __restrict__ step_type,
               const float* __restrict__ discount,
               const float* __restrict__ tvalue,
               float*       __restrict__ out)
{
    const int n = blockIdx.x * 512 + threadIdx.x;   // 0 .. 25599
    if (n < BB) out[(TT - 1) * BB + n] = 0.0f;      // loss[T-1] = 0
    if (n >= BQ) return;
    const int b = n / QQ;

    float carry = tvalue[(TT - 1) * BQ + n];
    #pragma unroll 4
    for (int t = TT - 2; t >= 0; --t) {
        float tv = tvalue[t * BQ + n];
        float r  = reward[(t + 1) * BB + b];
        float d  = discount[(t + 1) * BB + b] * GAMMA_F;
        bool  il = (step_type[t * BB + b] == 2);
        float acc = fmaf(carry, d, r);
        carry = il ? tv : acc;
        g_ret[t * BQ + n] = carry;
    }
}

// ---------------------------------------------------------------------------
// Kernel 2: pairwise quantile-Huber.
// Math: x = ret_i - v_j; c = clamp(x,-1,1); t = x - 0.5c;
//       h = c*t (>=0), signed h = |c|*t (since sign(x)*c = |c|).
//       loss_j = 0.5*S + (tau_j - 0.5)*D  with S = sum h, D = sum signed h.
// Packed f32x2 for the fma-pipe ops; scalar FMNMX for the clamp.
// ---------------------------------------------------------------------------

// Process 2 (i) pairs packed in one u64 of returns.
#define PAIR2(r2_) do {                                                        \
    unsigned long long x2_, c2_, t2_, a2_;                                     \
    asm("add.rn.f32x2 %0, %1, %2;" : "=l"(x2_) : "l"(r2_), "l"(nv2));          \
    float xa_, xb_;                                                            \
    asm("mov.b64 {%0, %1}, %2;" : "=f"(xa_), "=f"(xb_) : "l"(x2_));            \
    float ca_ = fminf(fmaxf(xa_, -1.0f), 1.0f);                                \
    float cb_ = fminf(fmaxf(xb_, -1.0f), 1.0f);                                \
    asm("mov.b64 %0, {%1, %2};" : "=l"(c2_) : "f"(ca_), "f"(cb_));             \
    asm("fma.rn.f32x2 %0, %1, %2, %3;" : "=l"(t2_)                             \
        : "l"(c2_), "l"(MH2), "l"(x2_));                                       \
    asm("fma.rn.f32x2 %0, %1, %2, %3;" : "=l"(acc2)                            \
        : "l"(c2_), "l"(t2_), "l"(acc2));                                      \
    asm("and.b64 %0, %1, 0x7FFFFFFF7FFFFFFF;" : "=l"(a2_) : "l"(c2_));         \
    asm("fma.rn.f32x2 %0, %1, %2, %3;" : "=l"(accs2)                           \
        : "l"(a2_), "l"(t2_), "l"(accs2));                                     \
} while (0)

__global__ __launch_bounds__(256)
void k_pairs(const float* __restrict__ value,
             float*       __restrict__ out)
{
    __shared__ __align__(16) float s_ret[UNITS][RST];
    __shared__ float s_part[UNITS][QQ];

    const int tid = threadIdx.x;
    const int gu0 = blockIdx.x * UNITS;

    // Stage returns rows for this block's units (coalesced: contiguous gmem).
    if (tid < UNITS * QQ) {
        const int u  = tid / QQ;
        const int q  = tid - u * QQ;
        const int gu = gu0 + u;
        if (gu < NUNITS) {
            const int t = gu / BB;
            const int b = gu - t * BB;
            s_ret[u][q] = g_ret[t * BQ + b * QQ + q];
        }
    }
    __syncthreads();

    if (tid < UNITS * QQ) {
        const int u  = tid / QQ;
        const int j  = tid - u * QQ;
        const int gu = gu0 + u;
        if (gu < NUNITS) {
            const int t = gu / BB;
            const int b = gu - t * BB;

            const float vj = value[t * BQ + b * QQ + j];
            unsigned long long nv2;
            {
                float nv = -vj;
                asm("mov.b64 %0, {%1, %1};" : "=l"(nv2) : "f"(nv));
            }
            const unsigned long long MH2 = 0xBF000000BF000000ULL; // (-0.5f,-0.5f)
            unsigned long long acc2 = 0ULL, accs2 = 0ULL;

            const ulonglong2* rp2 =
                reinterpret_cast<const ulonglong2*>(&s_ret[u][0]);
            #pragma unroll 4
            for (int p = 0; p < 12; ++p) {          // 48 returns via LDS.128
                ulonglong2 rr = rp2[p];
                PAIR2(rr.x);
                PAIR2(rr.y);
            }
            {                                        // returns 48,49
                unsigned long long rt_ =
                    *reinterpret_cast<const unsigned long long*>(&s_ret[u][48]);
                PAIR2(rt_);
            }

            float s_lo, s_hi, d_lo, d_hi;
            asm("mov.b64 {%0, %1}, %2;" : "=f"(s_lo), "=f"(s_hi) : "l"(acc2));
            asm("mov.b64 {%0, %1}, %2;" : "=f"(d_lo), "=f"(d_hi) : "l"(accs2));
            const float S = s_lo + s_hi;
            const float D = d_lo + d_hi;
            const float tau = ((float)j + 0.5f) * (1.0f / QQ);
            s_part[u][j] = fmaf(tau - 0.5f, D, 0.5f * S);
        }
    }
    __syncthreads();

    // Deterministic fixed-order j-reduction, one thread per unit.
    if (tid < UNITS) {
        const int gu = gu0 + tid;
        if (gu < NUNITS) {
            const int t = gu / BB;
            const int b = gu - t * BB;
            float s = 0.0f;
            #pragma unroll
            for (int j = 0; j < QQ; ++j) s += s_part[tid][j];
            out[t * BB + b] = s * (1.0f / QQ);
        }
    }
}

extern "C" void kernel_launch(void* const* d_in, const int* in_sizes, int n_in,
                              void* d_out, int out_size)
{
    const float* reward    = (const float*)d_in[0];
    const int*   step_type = (const int*)  d_in[1];
    const float* discount  = (const float*)d_in[2];
    const float* value     = (const float*)d_in[3];
    const float* tvalue    = (const float*)d_in[4];
    float*       out       = (float*)d_out;

    k_returns<<<50, 512>>>(reward, step_type, discount, tvalue, out);

    const int nblocks = (NUNITS + UNITS - 1) / UNITS;   // 13005
    k_pairs<<<nblocks, 256>>>(value, out);
}